// round 2
// baseline (speedup 1.0000x reference)
#include <cuda_runtime.h>
#include <math.h>

#define B      512
#define S      200
#define H      1024
#define V      100
#define EMB    512
#define INSZ   1024
#define H3     3072
#define START_TOK 1
#define NTH    256

// ---------------- persistent scratch ----------------
__device__ float g_decode[B * INSZ];
__device__ float g_h0[B * H];
__device__ float g_h1[B * H];
__device__ float g_h2[B * H];
__device__ float g_gi[B * H3];
__device__ float g_gh[B * H3];
__device__ float g_gi0c[B * H3];
__device__ float g_tokt[V * H3];
__device__ float g_logc[B * V];
__device__ unsigned g_bar_count;   // zero-init
__device__ unsigned g_bar_phase;   // monotonically increasing, survives replays

// ---------------- grid-wide barrier (sense-reversing) ----------------
__device__ __forceinline__ void grid_bar()
{
    __syncthreads();
    if (threadIdx.x == 0) {
        __threadfence();
        volatile unsigned* php = &g_bar_phase;
        unsigned ph = *php;
        if (atomicAdd(&g_bar_count, 1u) == gridDim.x - 1u) {
            g_bar_count = 0u;
            __threadfence();
            atomicAdd(&g_bar_phase, 1u);
        } else {
            while (*php == ph) { __nanosleep(64); }
        }
        __threadfence();
    }
    __syncthreads();
}

// ---------------- 64x64 GEMM tile: C = A @ W^T (+bias) (+Cadd) ----------------
struct TileJob {
    const float* A; const float* W; const float* bias; const float* Cadd;
    float* C;
    int lda, ldw, ldadd, ldc, M, N, K, m0, n0;
};

__device__ __forceinline__ TileJob mkjob(
    const float* A, int lda, const float* W, int ldw,
    const float* bias, const float* Cadd, int ldadd,
    float* C, int ldc, int M, int N, int K, int m0, int n0)
{
    TileJob t;
    t.A = A; t.W = W; t.bias = bias; t.Cadd = Cadd; t.C = C;
    t.lda = lda; t.ldw = ldw; t.ldadd = ldadd; t.ldc = ldc;
    t.M = M; t.N = N; t.K = K; t.m0 = m0; t.n0 = n0;
    return t;
}

__device__ __noinline__ void gemm_tile(TileJob jb, float* sA, float* sW)
{
    const int tid = threadIdx.x;
    const int ty = tid >> 4;     // 0..15  (m)
    const int tx = tid & 15;     // 0..15  (n)

    float acc[4][4];
#pragma unroll
    for (int i = 0; i < 4; i++)
#pragma unroll
        for (int jj = 0; jj < 4; jj++) acc[i][jj] = 0.0f;

    // loaders: tid<128 -> A (64 rows x 8 k), tid>=128 -> W (64 rows x 8 k)
    const int u  = tid & 127;
    const int lr = u >> 1;          // 0..63
    const int lk = (u & 1) * 4;     // 0 or 4
    const float* src;
    int valid;
    if (tid < 128) {
        int m = jb.m0 + lr;
        valid = (m < jb.M);
        src = jb.A + (size_t)m * jb.lda + lk;
    } else {
        int n = jb.n0 + lr;
        valid = (n < jb.N);
        src = jb.W + (size_t)n * jb.ldw + lk;
    }
    float* dst = ((tid < 128) ? sA : sW) + lk * 64 + lr;

    for (int k0 = 0; k0 < jb.K; k0 += 8) {
        float4 v = make_float4(0.f, 0.f, 0.f, 0.f);
        if (valid) v = *reinterpret_cast<const float4*>(src + k0);
        dst[0]       = v.x;
        dst[64]      = v.y;
        dst[2 * 64]  = v.z;
        dst[3 * 64]  = v.w;
        __syncthreads();

#pragma unroll
        for (int kk = 0; kk < 8; kk++) {
            float4 av = *reinterpret_cast<float4*>(&sA[kk * 64 + ty * 4]);
            float4 wv = *reinterpret_cast<float4*>(&sW[kk * 64 + tx * 4]);
            float ar[4] = {av.x, av.y, av.z, av.w};
            float wr[4] = {wv.x, wv.y, wv.z, wv.w};
#pragma unroll
            for (int i = 0; i < 4; i++)
#pragma unroll
                for (int jj = 0; jj < 4; jj++)
                    acc[i][jj] = fmaf(ar[i], wr[jj], acc[i][jj]);
        }
        __syncthreads();
    }

#pragma unroll
    for (int i = 0; i < 4; i++) {
        int m = jb.m0 + ty * 4 + i;
        if (m >= jb.M) continue;
        float* cr = jb.C + (size_t)m * jb.ldc;
        const float* ca = jb.Cadd ? (jb.Cadd + (size_t)m * jb.ldadd) : nullptr;
#pragma unroll
        for (int jj = 0; jj < 4; jj++) {
            int n = jb.n0 + tx * 4 + jj;
            if (n >= jb.N) continue;
            float vv = acc[i][jj];
            if (jb.bias) vv += jb.bias[n];
            if (ca) vv += ca[n];
            cr[n] = vv;
        }
    }
}

__device__ __forceinline__ float sigm(float x) { return 1.0f / (1.0f + expf(-x)); }

// ---------------- the single persistent kernel ----------------
__global__ __launch_bounds__(NTH, 2) void decoder_k(
    const int* __restrict__ inputs, const float* __restrict__ z,
    const float* __restrict__ cond, const float* __restrict__ emb,
    const float* __restrict__ i2h_w, const float* __restrict__ i2h_b,
    const float* __restrict__ out_w, const float* __restrict__ out_b,
    const float* __restrict__ wih0, const float* __restrict__ whh0,
    const float* __restrict__ bih0, const float* __restrict__ bhh0,
    const float* __restrict__ wih1, const float* __restrict__ whh1,
    const float* __restrict__ bih1, const float* __restrict__ bhh1,
    const float* __restrict__ wih2, const float* __restrict__ whh2,
    const float* __restrict__ bih2, const float* __restrict__ bhh2,
    float* __restrict__ out)
{
    __shared__ float sA[8 * 64];
    __shared__ float sW[8 * 64];
    const int tid = threadIdx.x;
    const unsigned nb = gridDim.x;

    // ---- P1: decode = concat(z, cond) ----
    for (int idx = blockIdx.x * NTH + tid; idx < B * INSZ; idx += nb * NTH) {
        int b = idx >> 10, jx = idx & 1023;
        g_decode[idx] = (jx < 512) ? z[b * 512 + jx] : cond[b * 512 + jx - 512];
    }
    grid_bar();

    // ---- P2: all decode-dependent precomputes ----
    {
        const int T1 = 128;        // h_init:  8 x 16 tiles   [512,1024,1024]
        const int T2 = T1 + 384;   // gi0c:    8 x 48         [512,3072,1024]
        const int T3 = T2 + 96;    // tokt:    2 x 48         [100,3072,512]
        const int T4 = T3 + 16;    // logc:    8 x 2          [512,100,1024]
        for (int w = blockIdx.x; w < T4; w += nb) {
            TileJob jb;
            if (w < T1) {
                int mt = w >> 4, nt = w & 15;
                jb = mkjob(g_decode, INSZ, i2h_w, INSZ, i2h_b, nullptr, 0,
                           g_h0, H, B, H, INSZ, mt * 64, nt * 64);
            } else if (w < T2) {
                int q = w - T1; int mt = q / 48, nt = q % 48;
                jb = mkjob(g_decode, INSZ, wih0 + EMB, EMB + INSZ, bih0, nullptr, 0,
                           g_gi0c, H3, B, H3, INSZ, mt * 64, nt * 64);
            } else if (w < T3) {
                int q = w - T2; int mt = q / 48, nt = q % 48;
                jb = mkjob(emb, EMB, wih0, EMB + INSZ, nullptr, nullptr, 0,
                           g_tokt, H3, V, H3, EMB, mt * 64, nt * 64);
            } else {
                int q = w - T3; int mt = q >> 1, nt = q & 1;
                jb = mkjob(g_decode, INSZ, out_w + H, H + INSZ, out_b, nullptr, 0,
                           g_logc, V, B, V, INSZ, mt * 64, nt * 64);
            }
            gemm_tile(jb, sA, sW);
        }
    }
    grid_bar();

    // ---- P3: broadcast h_init to all layers ----
    for (int idx = blockIdx.x * NTH + tid; idx < B * H; idx += nb * NTH) {
        float v = g_h0[idx];
        g_h1[idx] = v;
        g_h2[idx] = v;
    }
    grid_bar();

    // ---- recurrent loop ----
    for (int t = 0; t < S; t++) {
        // A: gh = h0 @ whh0^T + bhh0  (384 tiles)  +  logits(t-1) (16 tiles)
        {
            int ntiles = 384 + (t > 0 ? 16 : 0);
            for (int w = blockIdx.x; w < ntiles; w += nb) {
                TileJob jb;
                if (w < 384) {
                    int mt = w / 48, nt = w % 48;
                    jb = mkjob(g_h0, H, whh0, H, bhh0, nullptr, 0,
                               g_gh, H3, B, H3, H, mt * 64, nt * 64);
                } else {
                    int q = w - 384; int mt = q >> 1, nt = q & 1;
                    jb = mkjob(g_h2, H, out_w, H + INSZ, nullptr, g_logc, V,
                               out + (size_t)(t - 1) * V, S * V,
                               B, V, H, mt * 64, nt * 64);
                }
                gemm_tile(jb, sA, sW);
            }
        }
        grid_bar();

        // B: layer-0 GRU elementwise (input gates from token table + const part)
        for (int idx = blockIdx.x * NTH + tid; idx < B * H; idx += nb * NTH) {
            int b = idx >> 10, jx = idx & 1023;
            int tok = (t == 0) ? START_TOK : inputs[b * S + t - 1];
            const float* tr = g_tokt + (size_t)tok * H3;
            const float* gc = g_gi0c + (size_t)b * H3;
            const float* gr = g_gh   + (size_t)b * H3;
            float r  = sigm(tr[jx] + gc[jx] + gr[jx]);
            float zz = sigm(tr[H + jx] + gc[H + jx] + gr[H + jx]);
            float n  = tanhf(tr[2 * H + jx] + gc[2 * H + jx] + r * gr[2 * H + jx]);
            g_h0[idx] = (1.0f - zz) * n + zz * g_h0[idx];
        }
        grid_bar();

        // C: layer-1 dual GEMM (768 tiles)
        for (int w = blockIdx.x; w < 768; w += nb) {
            TileJob jb;
            if (w < 384) {
                int mt = w / 48, nt = w % 48;
                jb = mkjob(g_h0, H, wih1, H, bih1, nullptr, 0,
                           g_gi, H3, B, H3, H, mt * 64, nt * 64);
            } else {
                int q = w - 384; int mt = q / 48, nt = q % 48;
                jb = mkjob(g_h1, H, whh1, H, bhh1, nullptr, 0,
                           g_gh, H3, B, H3, H, mt * 64, nt * 64);
            }
            gemm_tile(jb, sA, sW);
        }
        grid_bar();

        // D: layer-1 GRU elementwise
        for (int idx = blockIdx.x * NTH + tid; idx < B * H; idx += nb * NTH) {
            int b = idx >> 10, jx = idx & 1023;
            const float* gb = g_gi + (size_t)b * H3;
            const float* gr = g_gh + (size_t)b * H3;
            float r  = sigm(gb[jx] + gr[jx]);
            float zz = sigm(gb[H + jx] + gr[H + jx]);
            float n  = tanhf(gb[2 * H + jx] + r * gr[2 * H + jx]);
            g_h1[idx] = (1.0f - zz) * n + zz * g_h1[idx];
        }
        grid_bar();

        // E: layer-2 dual GEMM (768 tiles)
        for (int w = blockIdx.x; w < 768; w += nb) {
            TileJob jb;
            if (w < 384) {
                int mt = w / 48, nt = w % 48;
                jb = mkjob(g_h1, H, wih2, H, bih2, nullptr, 0,
                           g_gi, H3, B, H3, H, mt * 64, nt * 64);
            } else {
                int q = w - 384; int mt = q / 48, nt = q % 48;
                jb = mkjob(g_h2, H, whh2, H, bhh2, nullptr, 0,
                           g_gh, H3, B, H3, H, mt * 64, nt * 64);
            }
            gemm_tile(jb, sA, sW);
        }
        grid_bar();

        // F: layer-2 GRU elementwise
        for (int idx = blockIdx.x * NTH + tid; idx < B * H; idx += nb * NTH) {
            int b = idx >> 10, jx = idx & 1023;
            const float* gb = g_gi + (size_t)b * H3;
            const float* gr = g_gh + (size_t)b * H3;
            float r  = sigm(gb[jx] + gr[jx]);
            float zz = sigm(gb[H + jx] + gr[H + jx]);
            float n  = tanhf(gb[2 * H + jx] + r * gr[2 * H + jx]);
            g_h2[idx] = (1.0f - zz) * n + zz * g_h2[idx];
        }
        grid_bar();
    }

    // ---- final logits for t = S-1 ----
    for (int w = blockIdx.x; w < 16; w += nb) {
        int mt = w >> 1, nt = w & 1;
        TileJob jb = mkjob(g_h2, H, out_w, H + INSZ, nullptr, g_logc, V,
                           out + (size_t)(S - 1) * V, S * V,
                           B, V, H, mt * 64, nt * 64);
        gemm_tile(jb, sA, sW);
    }
}

// ---------------- host launcher: ONE graph node ----------------
extern "C" void kernel_launch(void* const* d_in, const int* in_sizes, int n_in,
                              void* d_out, int out_size)
{
    (void)in_sizes; (void)n_in; (void)out_size;

    const int*   inputs = (const int*)  d_in[0];
    const float* z      = (const float*)d_in[1];
    const float* cond   = (const float*)d_in[2];
    // d_in[3] = temperature (teacher forcing always on)
    const float* emb    = (const float*)d_in[4];
    const float* i2h_w  = (const float*)d_in[5];
    const float* i2h_b  = (const float*)d_in[6];
    const float* out_w  = (const float*)d_in[7];
    const float* out_b  = (const float*)d_in[8];
    const float* wih0 = (const float*)d_in[9];
    const float* whh0 = (const float*)d_in[10];
    const float* bih0 = (const float*)d_in[11];
    const float* bhh0 = (const float*)d_in[12];
    const float* wih1 = (const float*)d_in[13];
    const float* whh1 = (const float*)d_in[14];
    const float* bih1 = (const float*)d_in[15];
    const float* bhh1 = (const float*)d_in[16];
    const float* wih2 = (const float*)d_in[17];
    const float* whh2 = (const float*)d_in[18];
    const float* bih2 = (const float*)d_in[19];
    const float* bhh2 = (const float*)d_in[20];
    float* out = (float*)d_out;

    int dev = 0;
    cudaGetDevice(&dev);
    int sms = 148;
    cudaDeviceGetAttribute(&sms, cudaDevAttrMultiProcessorCount, dev);
    int bpm = 1;
    cudaOccupancyMaxActiveBlocksPerMultiprocessor(&bpm, decoder_k, NTH, 0);
    if (bpm < 1) bpm = 1;

    decoder_k<<<sms * bpm, NTH>>>(
        inputs, z, cond, emb, i2h_w, i2h_b, out_w, out_b,
        wih0, whh0, bih0, bhh0, wih1, whh1, bih1, bhh1,
        wih2, whh2, bih2, bhh2, out);
}

// round 3
// speedup vs baseline: 2.2993x; 2.2993x over previous
#include <cuda_runtime.h>
#include <cstdint>
#include <math.h>

#define B      512
#define S      200
#define H      1024
#define V      100
#define EMB    512
#define INSZ   1024
#define H3     3072
#define START_TOK 1
#define NTH    128

#define SA_STRIDE 136   // floats; 16B-aligned rows, bank-shift 8
#define SW_STRIDE 68    // floats; 16B-aligned rows, bank-shift 4

// ---------------- persistent scratch ----------------
__device__ float g_decode[B * INSZ];
__device__ float g_h0[B * H];
__device__ float g_h1[B * H];
__device__ float g_h2[B * H];
__device__ float g_gi0[B * H3];
__device__ float g_gi1[B * H3];
__device__ float g_gh0[B * H3];
__device__ float g_gh1[B * H3];
__device__ float g_gh2[B * H3];
__device__ float g_gh3[B * H3];
__device__ float g_gi0c[B * H3];
__device__ float g_tokt[V * H3];
__device__ float g_logc[B * V];
__device__ unsigned g_bar_count;
__device__ unsigned g_bar_phase;

// ---------------- grid barrier ----------------
__device__ __forceinline__ void grid_bar()
{
    __syncthreads();
    if (threadIdx.x == 0) {
        __threadfence();
        volatile unsigned* php = &g_bar_phase;
        unsigned ph = *php;
        if (atomicAdd(&g_bar_count, 1u) == gridDim.x - 1u) {
            g_bar_count = 0u;
            __threadfence();
            atomicAdd(&g_bar_phase, 1u);
        } else {
            while (*php == ph) { __nanosleep(32); }
        }
        __threadfence();
    }
    __syncthreads();
}

// ---------------- f32x2 helpers ----------------
__device__ __forceinline__ unsigned long long pack2(float x)
{
    unsigned long long r;
    asm("mov.b64 %0, {%1, %1};" : "=l"(r) : "f"(x));
    return r;
}
__device__ __forceinline__ void fma2(unsigned long long& d, unsigned long long a,
                                     unsigned long long b)
{
    asm("fma.rn.f32x2 %0, %1, %2, %0;" : "+l"(d) : "l"(a), "l"(b));
}
__device__ __forceinline__ void unpack2(unsigned long long v, float& lo, float& hi)
{
    asm("mov.b64 {%0, %1}, %2;" : "=f"(lo), "=f"(hi) : "l"(v));
}
__device__ __forceinline__ void lds_v2u64(unsigned long long& x, unsigned long long& y,
                                          uint32_t a)
{
    asm volatile("ld.shared.v2.u64 {%0, %1}, [%2];" : "=l"(x), "=l"(y) : "r"(a));
}
__device__ __forceinline__ void sts_f32(uint32_t a, float v)
{
    asm volatile("st.shared.f32 [%0], %1;" :: "r"(a), "f"(v));
}

// ---------------- GEMM tile job ----------------
struct Job {
    const float* A; const float* W; const float* bias; const float* Cadd; float* C;
    int lda, ldw, ldadd, ldc, Mlim, Nlim, m0, n0, kbeg, klen;
};

__device__ __forceinline__ Job mkjob(
    const float* A, int lda, const float* W, int ldw,
    const float* bias, const float* Cadd, int ldadd,
    float* C, int ldc, int Mlim, int Nlim, int m0, int n0, int kbeg, int klen)
{
    Job j;
    j.A = A; j.W = W; j.bias = bias; j.Cadd = Cadd; j.C = C;
    j.lda = lda; j.ldw = ldw; j.ldadd = ldadd; j.ldc = ldc;
    j.Mlim = Mlim; j.Nlim = Nlim; j.m0 = m0; j.n0 = n0; j.kbeg = kbeg; j.klen = klen;
    return j;
}

// 128x64 tile, 128 threads, 8x8 per thread via f32x2, double-buffered
__device__ __noinline__ void gemm_tile(const Job jb, uint32_t sAb, uint32_t sWb)
{
    const int tid = threadIdx.x;
    const int ty = tid >> 3;        // 0..15 -> rows ty*8..+7
    const int tx = tid & 7;         // 0..7  -> cols tx*4 (+32 group)
    const int lrow = tid >> 2;      // 0..31 loader row
    const int lkq  = tid & 3;       // 0..3  loader k-quad

    // global loader pointers
    const float* aP[4]; bool aV[4];
#pragma unroll
    for (int f = 0; f < 4; f++) {
        int m = jb.m0 + f * 32 + lrow;
        aV[f] = (m < jb.Mlim);
        aP[f] = jb.A + (size_t)(aV[f] ? m : 0) * jb.lda + jb.kbeg + lkq * 4;
    }
    const float* wP[2]; bool wV[2];
#pragma unroll
    for (int f = 0; f < 2; f++) {
        int n = jb.n0 + f * 32 + lrow;
        wV[f] = (n < jb.Nlim);
        wP[f] = jb.W + (size_t)(wV[f] ? n : 0) * jb.ldw + jb.kbeg + lkq * 4;
    }

    // STS swizzled row bases (swizzle key = k>>2 = lkq)
    uint32_t stA[4], stW[2];
#pragma unroll
    for (int f = 0; f < 4; f++)
        stA[f] = sAb + (uint32_t)(((lkq * 4) * SA_STRIDE + (((f * 32) + lrow) ^ (lkq << 3))) << 2);
#pragma unroll
    for (int f = 0; f < 2; f++)
        stW[f] = sWb + (uint32_t)(((lkq * 4) * SW_STRIDE + (((f * 32) + lrow) ^ (lkq << 3))) << 2);

    const uint32_t bufA = (uint32_t)(16 * SA_STRIDE * 4);
    const uint32_t bufW = (uint32_t)(16 * SW_STRIDE * 4);

    unsigned long long acc[8][4];
#pragma unroll
    for (int i = 0; i < 8; i++)
#pragma unroll
        for (int j = 0; j < 4; j++) acc[i][j] = 0ull;

    float4 aR[4], wR[2];
    const float4 zero4 = make_float4(0.f, 0.f, 0.f, 0.f);

#define LOADG() do { \
    _Pragma("unroll") for (int f = 0; f < 4; f++) { \
        aR[f] = aV[f] ? *reinterpret_cast<const float4*>(aP[f]) : zero4; aP[f] += 16; } \
    _Pragma("unroll") for (int f = 0; f < 2; f++) { \
        wR[f] = wV[f] ? *reinterpret_cast<const float4*>(wP[f]) : zero4; wP[f] += 16; } \
} while (0)

#define STS(bsel) do { \
    uint32_t offa = (bsel) ? bufA : 0u; \
    uint32_t offw = (bsel) ? bufW : 0u; \
    _Pragma("unroll") for (int f = 0; f < 4; f++) { \
        uint32_t a0 = stA[f] + offa; \
        sts_f32(a0, aR[f].x); \
        sts_f32(a0 + SA_STRIDE * 4, aR[f].y); \
        sts_f32(a0 + SA_STRIDE * 8, aR[f].z); \
        sts_f32(a0 + SA_STRIDE * 12, aR[f].w); } \
    _Pragma("unroll") for (int f = 0; f < 2; f++) { \
        uint32_t a0 = stW[f] + offw; \
        sts_f32(a0, wR[f].x); \
        sts_f32(a0 + SW_STRIDE * 4, wR[f].y); \
        sts_f32(a0 + SW_STRIDE * 8, wR[f].z); \
        sts_f32(a0 + SW_STRIDE * 12, wR[f].w); } \
} while (0)

#define COMPUTE(bsel) do { \
    uint32_t baA = sAb + ((bsel) ? bufA : 0u); \
    uint32_t baW = sWb + ((bsel) ? bufW : 0u); \
    _Pragma("unroll") for (int kk = 0; kk < 16; kk++) { \
        uint32_t sw = (uint32_t)((kk >> 2) << 3); \
        uint32_t aad = baA + (uint32_t)((kk * SA_STRIDE + ((ty * 8) ^ sw)) << 2); \
        float4 av0, av1; \
        asm volatile("ld.shared.v4.f32 {%0,%1,%2,%3}, [%4];" \
            : "=f"(av0.x), "=f"(av0.y), "=f"(av0.z), "=f"(av0.w) : "r"(aad)); \
        asm volatile("ld.shared.v4.f32 {%0,%1,%2,%3}, [%4];" \
            : "=f"(av1.x), "=f"(av1.y), "=f"(av1.z), "=f"(av1.w) : "r"(aad + 16)); \
        unsigned long long w0, w1, w2, w3; \
        uint32_t wad0 = baW + (uint32_t)((kk * SW_STRIDE + ((tx * 4) ^ sw)) << 2); \
        uint32_t wad1 = baW + (uint32_t)((kk * SW_STRIDE + (((tx * 4) + 32) ^ sw)) << 2); \
        lds_v2u64(w0, w1, wad0); \
        lds_v2u64(w2, w3, wad1); \
        float as[8] = {av0.x, av0.y, av0.z, av0.w, av1.x, av1.y, av1.z, av1.w}; \
        _Pragma("unroll") for (int i = 0; i < 8; i++) { \
            unsigned long long ap = pack2(as[i]); \
            fma2(acc[i][0], ap, w0); \
            fma2(acc[i][1], ap, w1); \
            fma2(acc[i][2], ap, w2); \
            fma2(acc[i][3], ap, w3); } \
    } \
} while (0)

    const int nch = jb.klen >> 4;
    LOADG();
    STS(0);
    __syncthreads();
    int cur = 0;
    for (int c = 0; c < nch; c++) {
        if (c + 1 < nch) LOADG();
        COMPUTE(cur);
        if (c + 1 < nch) {
            STS(cur ^ 1);
            __syncthreads();
            cur ^= 1;
        }
    }
    __syncthreads();   // protect smem for next unit

#undef LOADG
#undef STS
#undef COMPUTE

    // epilogue
#pragma unroll
    for (int i = 0; i < 8; i++) {
        int m = jb.m0 + ty * 8 + i;
        if (m >= jb.Mlim) continue;
        float* cr = jb.C + (size_t)m * jb.ldc;
        const float* ca = jb.Cadd ? (jb.Cadd + (size_t)m * jb.ldadd) : nullptr;
#pragma unroll
        for (int g = 0; g < 2; g++) {
#pragma unroll
            for (int p = 0; p < 2; p++) {
                float lo, hi;
                unpack2(acc[i][g * 2 + p], lo, hi);
                int n = jb.n0 + g * 32 + tx * 4 + p * 2;
                if (n < jb.Nlim) {
                    float v = lo;
                    if (jb.bias) v += jb.bias[n];
                    if (ca) v += ca[n];
                    cr[n] = v;
                }
                if (n + 1 < jb.Nlim) {
                    float v = hi;
                    if (jb.bias) v += jb.bias[n + 1];
                    if (ca) v += ca[n + 1];
                    cr[n + 1] = v;
                }
            }
        }
    }
}

__device__ __forceinline__ float sigm(float x)
{
    return 1.0f / (1.0f + __expf(-x));
}

// ---------------- persistent kernel ----------------
__global__ __launch_bounds__(NTH, 4) void decoder_k(
    const int* __restrict__ inputs, const float* __restrict__ z,
    const float* __restrict__ cond, const float* __restrict__ emb,
    const float* __restrict__ i2h_w, const float* __restrict__ i2h_b,
    const float* __restrict__ out_w, const float* __restrict__ out_b,
    const float* __restrict__ wih0, const float* __restrict__ whh0,
    const float* __restrict__ bih0, const float* __restrict__ bhh0,
    const float* __restrict__ wih1, const float* __restrict__ whh1,
    const float* __restrict__ bih1, const float* __restrict__ bhh1,
    const float* __restrict__ wih2, const float* __restrict__ whh2,
    const float* __restrict__ bih2, const float* __restrict__ bhh2,
    float* __restrict__ out)
{
    __shared__ __align__(16) float shA[2 * 16 * SA_STRIDE];
    __shared__ __align__(16) float shW[2 * 16 * SW_STRIDE];
    const uint32_t sAb = (uint32_t)__cvta_generic_to_shared(&shA[0]);
    const uint32_t sWb = (uint32_t)__cvta_generic_to_shared(&shW[0]);

    const int tid = threadIdx.x;
    const unsigned nb = gridDim.x;
    const int gstride = nb * NTH;

    // ---- P1: decode = concat(z, cond) ----
    for (int idx = blockIdx.x * NTH + tid; idx < B * INSZ; idx += gstride) {
        int b = idx >> 10, jx = idx & 1023;
        g_decode[idx] = (jx < 512) ? z[b * 512 + jx] : cond[b * 512 + jx - 512];
    }
    grid_bar();

    // ---- P2: precomputes ----
    {
        // h_init 64 | gi0c 192 | tokt 48 | logc 8  => 312 units
        for (int u = blockIdx.x; u < 312; u += nb) {
            Job jb;
            if (u < 64) {
                int mt = u >> 4, nt = u & 15;
                jb = mkjob(g_decode, INSZ, i2h_w, INSZ, i2h_b, nullptr, 0,
                           g_h0, H, B, H, mt * 128, nt * 64, 0, INSZ);
            } else if (u < 256) {
                int q = u - 64, mt = q / 48, nt = q % 48;
                jb = mkjob(g_decode, INSZ, wih0 + EMB, EMB + INSZ, bih0, nullptr, 0,
                           g_gi0c, H3, B, H3, mt * 128, nt * 64, 0, INSZ);
            } else if (u < 304) {
                int nt = u - 256;
                jb = mkjob(emb, EMB, wih0, EMB + INSZ, nullptr, nullptr, 0,
                           g_tokt, H3, V, H3, 0, nt * 64, 0, EMB);
            } else {
                int q = u - 304, mt = q >> 1, nt = q & 1;
                jb = mkjob(g_decode, INSZ, out_w + H, H + INSZ, out_b, nullptr, 0,
                           g_logc, V, B, V, mt * 128, nt * 64, 0, INSZ);
            }
            gemm_tile(jb, sAb, sWb);
        }
    }
    grid_bar();

    // ---- P3: broadcast h_init ----
    for (int idx = blockIdx.x * NTH + tid; idx < B * H; idx += gstride) {
        float v = g_h0[idx];
        g_h1[idx] = v;
        g_h2[idx] = v;
    }
    grid_bar();

    float* ghp[4] = {g_gh0, g_gh1, g_gh2, g_gh3};

    // ---- recurrent loop ----
    for (int t = 0; t < S; t++) {
        // A: gh(l0) k-split-4 (768) + logits(t-1) (8)
        {
            int U = 768 + (t > 0 ? 8 : 0);
            for (int u = blockIdx.x; u < U; u += nb) {
                Job jb;
                if (u < 768) {
                    int ks = u & 3, r = u >> 2, mt = r / 48, nt = r % 48;
                    jb = mkjob(g_h0, H, whh0, H, ks == 0 ? bhh0 : nullptr,
                               nullptr, 0, ghp[ks], H3, B, H3,
                               mt * 128, nt * 64, ks * 256, 256);
                } else {
                    int q = u - 768, nt = q & 1, mt = q >> 1;
                    jb = mkjob(g_h2, H, out_w, H + INSZ, nullptr, g_logc, V,
                               out + (size_t)(t - 1) * V, S * V, B, V,
                               mt * 128, nt * 64, 0, H);
                }
                gemm_tile(jb, sAb, sWb);
            }
        }
        grid_bar();

        // B: layer-0 GRU elementwise
        for (int idx = blockIdx.x * NTH + tid; idx < B * H; idx += gstride) {
            int b = idx >> 10, jx = idx & 1023;
            int tok = (t == 0) ? START_TOK : inputs[b * S + t - 1];
            const float* tr = g_tokt + (size_t)tok * H3;
            size_t b3 = (size_t)b * H3;
            float hr = g_gh0[b3 + jx] + g_gh1[b3 + jx] + g_gh2[b3 + jx] + g_gh3[b3 + jx];
            float hz = g_gh0[b3 + H + jx] + g_gh1[b3 + H + jx] + g_gh2[b3 + H + jx] + g_gh3[b3 + H + jx];
            float hn = g_gh0[b3 + 2 * H + jx] + g_gh1[b3 + 2 * H + jx] + g_gh2[b3 + 2 * H + jx] + g_gh3[b3 + 2 * H + jx];
            float ir = tr[jx] + g_gi0c[b3 + jx];
            float iz = tr[H + jx] + g_gi0c[b3 + H + jx];
            float in_ = tr[2 * H + jx] + g_gi0c[b3 + 2 * H + jx];
            float r  = sigm(ir + hr);
            float zz = sigm(iz + hz);
            float n  = tanhf(in_ + r * hn);
            g_h0[idx] = (1.0f - zz) * n + zz * g_h0[idx];
        }
        grid_bar();

        // C: layer-1 dual, k-split-2 (768)
        for (int u = blockIdx.x; u < 768; u += nb) {
            int ks = u & 1, r = u >> 1, mt = r / 48, nt = r % 48;
            Job jb;
            if (mt < 4)
                jb = mkjob(g_h0, H, wih1, H, ks == 0 ? bih1 : nullptr, nullptr, 0,
                           ks ? g_gi1 : g_gi0, H3, B, H3,
                           mt * 128, nt * 64, ks * 512, 512);
            else
                jb = mkjob(g_h1, H, whh1, H, ks == 0 ? bhh1 : nullptr, nullptr, 0,
                           ks ? g_gh1 : g_gh0, H3, B, H3,
                           (mt - 4) * 128, nt * 64, ks * 512, 512);
            gemm_tile(jb, sAb, sWb);
        }
        grid_bar();

        // D: layer-1 elementwise
        for (int idx = blockIdx.x * NTH + tid; idx < B * H; idx += gstride) {
            int b = idx >> 10, jx = idx & 1023;
            size_t b3 = (size_t)b * H3;
            float ir = g_gi0[b3 + jx] + g_gi1[b3 + jx];
            float iz = g_gi0[b3 + H + jx] + g_gi1[b3 + H + jx];
            float in_ = g_gi0[b3 + 2 * H + jx] + g_gi1[b3 + 2 * H + jx];
            float hr = g_gh0[b3 + jx] + g_gh1[b3 + jx];
            float hz = g_gh0[b3 + H + jx] + g_gh1[b3 + H + jx];
            float hn = g_gh0[b3 + 2 * H + jx] + g_gh1[b3 + 2 * H + jx];
            float r  = sigm(ir + hr);
            float zz = sigm(iz + hz);
            float n  = tanhf(in_ + r * hn);
            g_h1[idx] = (1.0f - zz) * n + zz * g_h1[idx];
        }
        grid_bar();

        // E: layer-2 dual, k-split-2 (768)
        for (int u = blockIdx.x; u < 768; u += nb) {
            int ks = u & 1, r = u >> 1, mt = r / 48, nt = r % 48;
            Job jb;
            if (mt < 4)
                jb = mkjob(g_h1, H, wih2, H, ks == 0 ? bih2 : nullptr, nullptr, 0,
                           ks ? g_gi1 : g_gi0, H3, B, H3,
                           mt * 128, nt * 64, ks * 512, 512);
            else
                jb = mkjob(g_h2, H, whh2, H, ks == 0 ? bhh2 : nullptr, nullptr, 0,
                           ks ? g_gh1 : g_gh0, H3, B, H3,
                           (mt - 4) * 128, nt * 64, ks * 512, 512);
            gemm_tile(jb, sAb, sWb);
        }
        grid_bar();

        // F: layer-2 elementwise
        for (int idx = blockIdx.x * NTH + tid; idx < B * H; idx += gstride) {
            int b = idx >> 10, jx = idx & 1023;
            size_t b3 = (size_t)b * H3;
            float ir = g_gi0[b3 + jx] + g_gi1[b3 + jx];
            float iz = g_gi0[b3 + H + jx] + g_gi1[b3 + H + jx];
            float in_ = g_gi0[b3 + 2 * H + jx] + g_gi1[b3 + 2 * H + jx];
            float hr = g_gh0[b3 + jx] + g_gh1[b3 + jx];
            float hz = g_gh0[b3 + H + jx] + g_gh1[b3 + H + jx];
            float hn = g_gh0[b3 + 2 * H + jx] + g_gh1[b3 + 2 * H + jx];
            float r  = sigm(ir + hr);
            float zz = sigm(iz + hz);
            float n  = tanhf(in_ + r * hn);
            g_h2[idx] = (1.0f - zz) * n + zz * g_h2[idx];
        }
        grid_bar();
    }

    // ---- final logits (t = S-1) ----
    for (int u = blockIdx.x; u < 8; u += nb) {
        int nt = u & 1, mt = u >> 1;
        Job jb = mkjob(g_h2, H, out_w, H + INSZ, nullptr, g_logc, V,
                       out + (size_t)(S - 1) * V, S * V, B, V,
                       mt * 128, nt * 64, 0, H);
        gemm_tile(jb, sAb, sWb);
    }
}

// ---------------- host ----------------
extern "C" void kernel_launch(void* const* d_in, const int* in_sizes, int n_in,
                              void* d_out, int out_size)
{
    (void)in_sizes; (void)n_in; (void)out_size;

    const int*   inputs = (const int*)  d_in[0];
    const float* z      = (const float*)d_in[1];
    const float* cond   = (const float*)d_in[2];
    const float* emb    = (const float*)d_in[4];
    const float* i2h_w  = (const float*)d_in[5];
    const float* i2h_b  = (const float*)d_in[6];
    const float* out_w  = (const float*)d_in[7];
    const float* out_b  = (const float*)d_in[8];
    const float* wih0 = (const float*)d_in[9];
    const float* whh0 = (const float*)d_in[10];
    const float* bih0 = (const float*)d_in[11];
    const float* bhh0 = (const float*)d_in[12];
    const float* wih1 = (const float*)d_in[13];
    const float* whh1 = (const float*)d_in[14];
    const float* bih1 = (const float*)d_in[15];
    const float* bhh1 = (const float*)d_in[16];
    const float* wih2 = (const float*)d_in[17];
    const float* whh2 = (const float*)d_in[18];
    const float* bih2 = (const float*)d_in[19];
    const float* bhh2 = (const float*)d_in[20];
    float* out = (float*)d_out;

    int dev = 0;
    cudaGetDevice(&dev);
    int sms = 148;
    cudaDeviceGetAttribute(&sms, cudaDevAttrMultiProcessorCount, dev);
    int bpm = 1;
    cudaOccupancyMaxActiveBlocksPerMultiprocessor(&bpm, decoder_k, NTH, 0);
    if (bpm < 1) bpm = 1;

    decoder_k<<<sms * bpm, NTH>>>(
        inputs, z, cond, emb, i2h_w, i2h_b, out_w, out_b,
        wih0, whh0, bih0, bhh0, wih1, whh1, bih1, bhh1,
        wih2, whh2, bih2, bhh2, out);
}